// round 5
// baseline (speedup 1.0000x reference)
#include <cuda_runtime.h>
#include <cuda_bf16.h>
#include <math.h>

// ---------------------------------------------------------------------------
// EncoderBlock: pre-norm transformer block, fp32, FFMA2 (f32x2) math,
// double-buffered dynamic-smem GEMM. B=2, S=2048, D=1024, H=16, DK=64, DFF=4096
// ---------------------------------------------------------------------------

#define NTOK   4096        // B*S
#define DM     1024
#define DFF    4096
#define NH     16
#define DK     64
#define SEQ    2048

typedef unsigned long long u64;

__device__ __forceinline__ u64 ffma2(u64 a, u64 b, u64 c) {
    u64 d;
    asm("fma.rn.f32x2 %0, %1, %2, %3;" : "=l"(d) : "l"(a), "l"(b), "l"(c));
    return d;
}
__device__ __forceinline__ u64 fmul2(u64 a, u64 b) {
    u64 d;
    asm("mul.rn.f32x2 %0, %1, %2;" : "=l"(d) : "l"(a), "l"(b));
    return d;
}
__device__ __forceinline__ u64 pack_dup(float x) {
    u64 r;
    asm("mov.b64 %0, {%1, %1};" : "=l"(r) : "f"(x));
    return r;
}
__device__ __forceinline__ float lo2(u64 v) { return __uint_as_float((unsigned)v); }
__device__ __forceinline__ float hi2(u64 v) { return __uint_as_float((unsigned)(v >> 32)); }

// scratch (static device globals; no allocations allowed)
__device__ float g_xn [NTOK * DM];
__device__ float g_q  [NTOK * DM];
__device__ float g_k  [NTOK * DM];
__device__ float g_v  [NTOK * DM];
__device__ float g_att[NTOK * DM];
__device__ float g_x1 [NTOK * DM];
__device__ float g_xn2[NTOK * DM];
__device__ float g_ff [NTOK * DFF];

// ---------------------------------------------------------------------------
// LayerNorm (faithful: unbiased variance ddof=1, eps added to std, scalar affine)
// ---------------------------------------------------------------------------
__global__ __launch_bounds__(256)
void ln_kernel(const float* __restrict__ x, float* __restrict__ out,
               const float* __restrict__ ap, const float* __restrict__ bp)
{
    __shared__ float red[8];
    const int row = blockIdx.x;
    const int t   = threadIdx.x;
    const float* xr = x + (size_t)row * DM;

    float v[4];
    float s = 0.f;
#pragma unroll
    for (int e = 0; e < 4; e++) {
        v[e] = xr[t + e * 256];
        s += v[e];
    }
#pragma unroll
    for (int off = 16; off > 0; off >>= 1)
        s += __shfl_xor_sync(0xffffffffu, s, off);
    if ((t & 31) == 0) red[t >> 5] = s;
    __syncthreads();
    float tot = 0.f;
#pragma unroll
    for (int i = 0; i < 8; i++) tot += red[i];
    const float mean = tot * (1.0f / DM);

    float sq = 0.f;
#pragma unroll
    for (int e = 0; e < 4; e++) {
        float d = v[e] - mean;
        sq += d * d;
    }
#pragma unroll
    for (int off = 16; off > 0; off >>= 1)
        sq += __shfl_xor_sync(0xffffffffu, sq, off);
    __syncthreads();
    if ((t & 31) == 0) red[t >> 5] = sq;
    __syncthreads();
    float sqtot = 0.f;
#pragma unroll
    for (int i = 0; i < 8; i++) sqtot += red[i];

    const float var   = sqtot * (1.0f / (DM - 1));   // ddof=1
    const float denom = sqrtf(var) + 1e-5f;          // eps on std
    const float sc    = ap[0] / denom;
    const float beta  = bp[0];

    float* orow = out + (size_t)row * DM;
#pragma unroll
    for (int e = 0; e < 4; e++)
        orow[t + e * 256] = (v[e] - mean) * sc + beta;
}

// ---------------------------------------------------------------------------
// GEMM: C[M,N] = A[M,K] @ W[N,K]^T + bias[N] (+res[M,N]) (relu?)
// 128x128x16 tiles, 256 threads, 8x8 register blocking via FFMA2,
// double-buffered DYNAMIC smem (50,176 B > 48 KB static limit).
// A tile stored DUPLICATED in smem (As2[k][2m]=As2[k][2m+1]=a) so broadcast
// pairs load with LDS.128. W tile transposed, natural pairs along n.
// ---------------------------------------------------------------------------
#define BM 128
#define BN 128
#define BK 16
#define A2S (2 * BM + 4)      // 260 floats: rows 16B-aligned
#define WS_ (BN + 4)          // 132 floats
#define A2S_STAGE (BK * A2S)                 // 4160 floats per stage
#define WS_STAGE  (BK * WS_)                 // 2112 floats per stage
#define GEMM_SMEM_FLOATS (2 * A2S_STAGE + 2 * WS_STAGE)   // 12544 floats
#define GEMM_SMEM_BYTES  (GEMM_SMEM_FLOATS * 4)           // 50176 bytes

__device__ __forceinline__
void gemm_body(const float* __restrict__ A, const float* __restrict__ W,
               const float* __restrict__ bias, const float* __restrict__ res,
               float* __restrict__ C, int m0, int n0, int N, int K, int relu,
               float* __restrict__ smem)
{
    // dynamic smem partition: [2][BK][A2S] then [2][BK][WS_]
    float* As2base = smem;                    // 2 * 4160 floats
    float* Wsbase  = smem + 2 * A2S_STAGE;    // 2 * 2112 floats

    const int t  = threadIdx.x;
    const int tx = t & 15;
    const int ty = t >> 4;

    u64 acc2[8][4];
#pragma unroll
    for (int i = 0; i < 8; i++)
#pragma unroll
        for (int j = 0; j < 4; j++) acc2[i][j] = 0ULL;

    const int lr = t >> 2;          // 0..63 row-in-group
    const int lc = (t & 3) << 2;    // 0,4,8,12 : k offset
    const int r0 = lr, r1 = lr + 64;

    const float* Ap0 = A + (size_t)(m0 + r0) * K + lc;
    const float* Ap1 = A + (size_t)(m0 + r1) * K + lc;
    const float* Wp0 = W + (size_t)(n0 + r0) * K + lc;
    const float* Wp1 = W + (size_t)(n0 + r1) * K + lc;

    // stage 0: load + store tile 0
    {
        float4 a0 = *(const float4*)Ap0;
        float4 a1 = *(const float4*)Ap1;
        float4 w0 = *(const float4*)Wp0;
        float4 w1 = *(const float4*)Wp1;
        float* As = As2base;             // stage 0
        float* Ws = Wsbase;
        *(u64*)&As[(lc + 0) * A2S + 2 * r0] = pack_dup(a0.x);
        *(u64*)&As[(lc + 1) * A2S + 2 * r0] = pack_dup(a0.y);
        *(u64*)&As[(lc + 2) * A2S + 2 * r0] = pack_dup(a0.z);
        *(u64*)&As[(lc + 3) * A2S + 2 * r0] = pack_dup(a0.w);
        *(u64*)&As[(lc + 0) * A2S + 2 * r1] = pack_dup(a1.x);
        *(u64*)&As[(lc + 1) * A2S + 2 * r1] = pack_dup(a1.y);
        *(u64*)&As[(lc + 2) * A2S + 2 * r1] = pack_dup(a1.z);
        *(u64*)&As[(lc + 3) * A2S + 2 * r1] = pack_dup(a1.w);
        Ws[(lc + 0) * WS_ + r0] = w0.x; Ws[(lc + 1) * WS_ + r0] = w0.y;
        Ws[(lc + 2) * WS_ + r0] = w0.z; Ws[(lc + 3) * WS_ + r0] = w0.w;
        Ws[(lc + 0) * WS_ + r1] = w1.x; Ws[(lc + 1) * WS_ + r1] = w1.y;
        Ws[(lc + 2) * WS_ + r1] = w1.z; Ws[(lc + 3) * WS_ + r1] = w1.w;
    }
    __syncthreads();

    int buf = 0;
    for (int k0 = 0; k0 < K; k0 += BK) {
        // prefetch next tile from gmem (registers)
        float4 pa0, pa1, pw0, pw1;
        const bool more = (k0 + BK < K);
        if (more) {
            pa0 = *(const float4*)(Ap0 + k0 + BK);
            pa1 = *(const float4*)(Ap1 + k0 + BK);
            pw0 = *(const float4*)(Wp0 + k0 + BK);
            pw1 = *(const float4*)(Wp1 + k0 + BK);
        }

        // compute current tile
        const float* As = As2base + buf * A2S_STAGE;
        const float* Ws = Wsbase  + buf * WS_STAGE;
#pragma unroll
        for (int kk = 0; kk < BK; kk++) {
            const ulonglong2* ap = (const ulonglong2*)&As[kk * A2S + ty * 16];
            const ulonglong2* wp = (const ulonglong2*)&Ws[kk * WS_ + tx * 8];
            ulonglong2 a01 = ap[0], a23 = ap[1], a45 = ap[2], a67 = ap[3];
            ulonglong2 w01 = wp[0], w23 = wp[1];
            u64 av[8] = {a01.x, a01.y, a23.x, a23.y, a45.x, a45.y, a67.x, a67.y};
            u64 wv[4] = {w01.x, w01.y, w23.x, w23.y};
#pragma unroll
            for (int i = 0; i < 8; i++)
#pragma unroll
                for (int j = 0; j < 4; j++)
                    acc2[i][j] = ffma2(av[i], wv[j], acc2[i][j]);
        }

        // store next tile into the other stage, single barrier
        if (more) {
            const int nbuf = buf ^ 1;
            float* Asn = As2base + nbuf * A2S_STAGE;
            float* Wsn = Wsbase  + nbuf * WS_STAGE;
            *(u64*)&Asn[(lc + 0) * A2S + 2 * r0] = pack_dup(pa0.x);
            *(u64*)&Asn[(lc + 1) * A2S + 2 * r0] = pack_dup(pa0.y);
            *(u64*)&Asn[(lc + 2) * A2S + 2 * r0] = pack_dup(pa0.z);
            *(u64*)&Asn[(lc + 3) * A2S + 2 * r0] = pack_dup(pa0.w);
            *(u64*)&Asn[(lc + 0) * A2S + 2 * r1] = pack_dup(pa1.x);
            *(u64*)&Asn[(lc + 1) * A2S + 2 * r1] = pack_dup(pa1.y);
            *(u64*)&Asn[(lc + 2) * A2S + 2 * r1] = pack_dup(pa1.z);
            *(u64*)&Asn[(lc + 3) * A2S + 2 * r1] = pack_dup(pa1.w);
            Wsn[(lc + 0) * WS_ + r0] = pw0.x; Wsn[(lc + 1) * WS_ + r0] = pw0.y;
            Wsn[(lc + 2) * WS_ + r0] = pw0.z; Wsn[(lc + 3) * WS_ + r0] = pw0.w;
            Wsn[(lc + 0) * WS_ + r1] = pw1.x; Wsn[(lc + 1) * WS_ + r1] = pw1.y;
            Wsn[(lc + 2) * WS_ + r1] = pw1.z; Wsn[(lc + 3) * WS_ + r1] = pw1.w;
            __syncthreads();
            buf = nbuf;
        }
    }

    // epilogue: unpack, bias (+res) (+relu), vector store
    const int nb = n0 + tx * 8;
    float4 b0 = *(const float4*)(bias + nb);
    float4 b1 = *(const float4*)(bias + nb + 4);
#pragma unroll
    for (int i = 0; i < 8; i++) {
        const int m = m0 + ty * 8 + i;
        float c[8];
        c[0] = lo2(acc2[i][0]) + b0.x; c[1] = hi2(acc2[i][0]) + b0.y;
        c[2] = lo2(acc2[i][1]) + b0.z; c[3] = hi2(acc2[i][1]) + b0.w;
        c[4] = lo2(acc2[i][2]) + b1.x; c[5] = hi2(acc2[i][2]) + b1.y;
        c[6] = lo2(acc2[i][3]) + b1.z; c[7] = hi2(acc2[i][3]) + b1.w;
        if (res) {
            const float4 q0 = *(const float4*)(res + (size_t)m * N + nb);
            const float4 q1 = *(const float4*)(res + (size_t)m * N + nb + 4);
            c[0] += q0.x; c[1] += q0.y; c[2] += q0.z; c[3] += q0.w;
            c[4] += q1.x; c[5] += q1.y; c[6] += q1.z; c[7] += q1.w;
        }
        if (relu) {
#pragma unroll
            for (int j = 0; j < 8; j++) c[j] = fmaxf(c[j], 0.f);
        }
        *(float4*)(C + (size_t)m * N + nb)     = make_float4(c[0], c[1], c[2], c[3]);
        *(float4*)(C + (size_t)m * N + nb + 4) = make_float4(c[4], c[5], c[6], c[7]);
    }
}

__global__ __launch_bounds__(256)
void gemm_kernel(const float* __restrict__ A, const float* __restrict__ W,
                 const float* __restrict__ bias, const float* __restrict__ res,
                 float* __restrict__ C, int M, int N, int K, int relu)
{
    extern __shared__ float dynsmem[];
    gemm_body(A, W, bias, res, C,
              blockIdx.y * BM, blockIdx.x * BN, N, K, relu, dynsmem);
}

// fused QKV: blockIdx.x in [0,24): 8 N-tiles per matrix (N=1024 each)
__global__ __launch_bounds__(256)
void qkv_kernel(const float* __restrict__ A,
                const float* __restrict__ wq, const float* __restrict__ bq,
                const float* __restrict__ wk, const float* __restrict__ bk,
                const float* __restrict__ wv, const float* __restrict__ bv,
                float* __restrict__ q, float* __restrict__ k, float* __restrict__ v)
{
    extern __shared__ float dynsmem[];

    const int mat = blockIdx.x >> 3;          // 0: q, 1: k, 2: v
    const int n0  = (blockIdx.x & 7) * BN;

    const float* W    = (mat == 0) ? wq : (mat == 1) ? wk : wv;
    const float* bias = (mat == 0) ? bq : (mat == 1) ? bk : bv;
    float*       C    = (mat == 0) ? q  : (mat == 1) ? k  : v;

    gemm_body(A, W, bias, nullptr, C,
              blockIdx.y * BM, n0, DM, DM, 0, dynsmem);
}

// ---------------------------------------------------------------------------
// Flash-style attention. grid = (S/64, H, B), 256 threads (16x16).
// 64 queries/block, 32 key tiles of 64, online softmax, FFMA2 mainloops.
// smem (~69.9 KB dynamic): Qs[d][i] Ks[d][j] Vs[j][d] Ps[j][i] all 64x68, Ms[64]
// ---------------------------------------------------------------------------
__global__ __launch_bounds__(256)
void attn_kernel(const float* __restrict__ q, const float* __restrict__ k,
                 const float* __restrict__ v, const int* __restrict__ mask,
                 float* __restrict__ out)
{
    extern __shared__ float sm[];
    float* Qs = sm;                 // [64][68] transposed (Qs[d*68+i])
    float* Ks = Qs + 64 * 68;       // [64][68] transposed (Ks[d*68+j])
    float* Vs = Ks + 64 * 68;       // [64][68] natural    (Vs[j*68+d])
    float* Ps = Vs + 64 * 68;       // [64][68] transposed (Ps[j*68+i])
    int*   Ms = (int*)(Ps + 64 * 68);

    const int b  = blockIdx.z;
    const int h  = blockIdx.y;
    const int qt = blockIdx.x;
    const int t  = threadIdx.x;
    const int tx = t & 15;
    const int ty = t >> 4;
    const float scale = 0.125f;     // 1/sqrt(64)

    const size_t base = (size_t)b * SEQ * DM + h * DK;

#pragma unroll
    for (int e = 0; e < 16; e++) {
        const int lin = e * 256 + t;
        const int i = lin >> 6, d = lin & 63;
        Qs[d * 68 + i] = q[base + (size_t)(qt * 64 + i) * DM + d];
    }

    float m_i[4], l_i[4];
    u64 o2[4][2];
#pragma unroll
    for (int a = 0; a < 4; a++) {
        m_i[a] = -INFINITY; l_i[a] = 0.f;
        o2[a][0] = 0ULL; o2[a][1] = 0ULL;
    }

    for (int kt = 0; kt < SEQ / 64; kt++) {
        __syncthreads();   // previous iter's Ps/Vs readers done
#pragma unroll
        for (int e = 0; e < 16; e++) {
            const int lin = e * 256 + t;
            const int j = lin >> 6, d = lin & 63;
            Ks[d * 68 + j] = k[base + (size_t)(kt * 64 + j) * DM + d];
            Vs[j * 68 + d] = v[base + (size_t)(kt * 64 + j) * DM + d];
        }
        if (t < 64) Ms[t] = mask[b * SEQ + kt * 64 + t];
        __syncthreads();

        // S = Q K^T : s2[a][c2], pairs along key dim
        u64 s2[4][2];
#pragma unroll
        for (int a = 0; a < 4; a++) { s2[a][0] = 0ULL; s2[a][1] = 0ULL; }
#pragma unroll
        for (int d = 0; d < 64; d++) {
            float4 qa = *(const float4*)&Qs[d * 68 + ty * 4];
            ulonglong2 kb = *(const ulonglong2*)&Ks[d * 68 + tx * 4];
            u64 q2[4] = {pack_dup(qa.x), pack_dup(qa.y), pack_dup(qa.z), pack_dup(qa.w)};
#pragma unroll
            for (int a = 0; a < 4; a++) {
                s2[a][0] = ffma2(q2[a], kb.x, s2[a][0]);
                s2[a][1] = ffma2(q2[a], kb.y, s2[a][1]);
            }
        }

        float s[4][4];
#pragma unroll
        for (int a = 0; a < 4; a++) {
            s[a][0] = lo2(s2[a][0]); s[a][1] = hi2(s2[a][0]);
            s[a][2] = lo2(s2[a][1]); s[a][3] = hi2(s2[a][1]);
#pragma unroll
            for (int c = 0; c < 4; c++) {
                float sv = s[a][c] * scale;
                if (Ms[tx * 4 + c] == 0) sv = -1e9f;
                s[a][c] = sv;
            }
        }

        // row max across 16 tx lanes
        float mt[4];
#pragma unroll
        for (int a = 0; a < 4; a++) {
            mt[a] = fmaxf(fmaxf(s[a][0], s[a][1]), fmaxf(s[a][2], s[a][3]));
#pragma unroll
            for (int off = 1; off <= 8; off <<= 1)
                mt[a] = fmaxf(mt[a], __shfl_xor_sync(0xffffffffu, mt[a], off));
        }

#pragma unroll
        for (int a = 0; a < 4; a++) {
            const float mnew = fmaxf(m_i[a], mt[a]);
            float ps = 0.f;
#pragma unroll
            for (int c = 0; c < 4; c++) {
                const float p = __expf(s[a][c] - mnew);
                s[a][c] = p;
                ps += p;
            }
#pragma unroll
            for (int off = 1; off <= 8; off <<= 1)
                ps += __shfl_xor_sync(0xffffffffu, ps, off);
            const float f = __expf(m_i[a] - mnew);
            l_i[a] = l_i[a] * f + ps;
            m_i[a] = mnew;
            const u64 f2 = pack_dup(f);
            o2[a][0] = fmul2(o2[a][0], f2);
            o2[a][1] = fmul2(o2[a][1], f2);
        }

        // stage P transposed
#pragma unroll
        for (int a = 0; a < 4; a++)
#pragma unroll
            for (int c = 0; c < 4; c++)
                Ps[(tx * 4 + c) * 68 + ty * 4 + a] = s[a][c];
        __syncthreads();

        // O += P V : pairs along head dim
#pragma unroll
        for (int j = 0; j < 64; j++) {
            float4 pa = *(const float4*)&Ps[j * 68 + ty * 4];
            ulonglong2 vb = *(const ulonglong2*)&Vs[j * 68 + tx * 4];
            u64 p2[4] = {pack_dup(pa.x), pack_dup(pa.y), pack_dup(pa.z), pack_dup(pa.w)};
#pragma unroll
            for (int a = 0; a < 4; a++) {
                o2[a][0] = ffma2(p2[a], vb.x, o2[a][0]);
                o2[a][1] = ffma2(p2[a], vb.y, o2[a][1]);
            }
        }
    }

#pragma unroll
    for (int a = 0; a < 4; a++) {
        const float inv = 1.0f / l_i[a];
        const int qrow = qt * 64 + ty * 4 + a;
        float* op = out + ((size_t)b * SEQ + qrow) * DM + h * DK + tx * 4;
        op[0] = lo2(o2[a][0]) * inv;
        op[1] = hi2(o2[a][0]) * inv;
        op[2] = lo2(o2[a][1]) * inv;
        op[3] = hi2(o2[a][1]) * inv;
    }
}

// ---------------------------------------------------------------------------
// launcher
// ---------------------------------------------------------------------------
extern "C" void kernel_launch(void* const* d_in, const int* in_sizes, int n_in,
                              void* d_out, int out_size)
{
    (void)in_sizes; (void)n_in; (void)out_size;

    const float* x    = (const float*)d_in[0];
    const int*   mask = (const int*)  d_in[1];
    const float* wq   = (const float*)d_in[2];
    const float* bq   = (const float*)d_in[3];
    const float* wk   = (const float*)d_in[4];
    const float* bk   = (const float*)d_in[5];
    const float* wv   = (const float*)d_in[6];
    const float* bv   = (const float*)d_in[7];
    const float* wo   = (const float*)d_in[8];
    const float* bo   = (const float*)d_in[9];
    const float* w1   = (const float*)d_in[10];
    const float* b1   = (const float*)d_in[11];
    const float* w2   = (const float*)d_in[12];
    const float* b2   = (const float*)d_in[13];
    const float* a1   = (const float*)d_in[14];
    const float* n1   = (const float*)d_in[15];
    const float* a2   = (const float*)d_in[16];
    const float* n2   = (const float*)d_in[17];
    float* out = (float*)d_out;

    float *xn, *q, *k, *v, *att, *x1, *xn2, *ff;
    cudaGetSymbolAddress((void**)&xn,  g_xn);
    cudaGetSymbolAddress((void**)&q,   g_q);
    cudaGetSymbolAddress((void**)&k,   g_k);
    cudaGetSymbolAddress((void**)&v,   g_v);
    cudaGetSymbolAddress((void**)&att, g_att);
    cudaGetSymbolAddress((void**)&x1,  g_x1);
    cudaGetSymbolAddress((void**)&xn2, g_xn2);
    cudaGetSymbolAddress((void**)&ff,  g_ff);

    const int attn_smem = (4 * 64 * 68) * 4 + 64 * 4;   // ~69.9 KB
    cudaFuncSetAttribute((const void*)attn_kernel,
                         cudaFuncAttributeMaxDynamicSharedMemorySize, attn_smem);
    cudaFuncSetAttribute((const void*)gemm_kernel,
                         cudaFuncAttributeMaxDynamicSharedMemorySize, GEMM_SMEM_BYTES);
    cudaFuncSetAttribute((const void*)qkv_kernel,
                         cudaFuncAttributeMaxDynamicSharedMemorySize, GEMM_SMEM_BYTES);

    // LN1
    ln_kernel<<<NTOK, 256>>>(x, xn, a1, n1);

    // fused Q,K,V projections
    {
        dim3 g(24, NTOK / BM);
        qkv_kernel<<<g, 256, GEMM_SMEM_BYTES>>>(xn, wq, bq, wk, bk, wv, bv, q, k, v);
    }

    // attention
    {
        dim3 g(SEQ / 64, NH, 2);
        attn_kernel<<<g, 256, attn_smem>>>(q, k, v, mask, att);
    }

    // O projection + residual
    {
        dim3 g(DM / BN, NTOK / BM);
        gemm_kernel<<<g, 256, GEMM_SMEM_BYTES>>>(att, wo, bo, x, x1, NTOK, DM, DM, 0);
    }

    // LN2
    ln_kernel<<<NTOK, 256>>>(x1, xn2, a2, n2);

    // FFN
    {
        dim3 g1(DFF / BN, NTOK / BM);
        gemm_kernel<<<g1, 256, GEMM_SMEM_BYTES>>>(xn2, w1, b1, nullptr, ff, NTOK, DFF, DM, 1);
        dim3 g2(DM / BN, NTOK / BM);
        gemm_kernel<<<g2, 256, GEMM_SMEM_BYTES>>>(ff, w2, b2, x1, out, NTOK, DM, DFF, 0);
    }
}

// round 7
// speedup vs baseline: 1.1556x; 1.1556x over previous
#include <cuda_runtime.h>
#include <cuda_bf16.h>
#include <math.h>

// ---------------------------------------------------------------------------
// EncoderBlock: pre-norm transformer block, fp32, FFMA2 (f32x2) math,
// double-buffered smem GEMM (normal A layout + register pack_dup broadcast).
// B=2, S=2048, D=1024, H=16, DK=64, DFF=4096
// ---------------------------------------------------------------------------

#define NTOK   4096        // B*S
#define DM     1024
#define DFF    4096
#define NH     16
#define DK     64
#define SEQ    2048

typedef unsigned long long u64;

__device__ __forceinline__ u64 ffma2(u64 a, u64 b, u64 c) {
    u64 d;
    asm("fma.rn.f32x2 %0, %1, %2, %3;" : "=l"(d) : "l"(a), "l"(b), "l"(c));
    return d;
}
__device__ __forceinline__ u64 fmul2(u64 a, u64 b) {
    u64 d;
    asm("mul.rn.f32x2 %0, %1, %2;" : "=l"(d) : "l"(a), "l"(b));
    return d;
}
__device__ __forceinline__ u64 pack_dup(float x) {
    u64 r;
    asm("mov.b64 %0, {%1, %1};" : "=l"(r) : "f"(x));
    return r;
}
__device__ __forceinline__ float lo2(u64 v) { return __uint_as_float((unsigned)v); }
__device__ __forceinline__ float hi2(u64 v) { return __uint_as_float((unsigned)(v >> 32)); }

// scratch (static device globals; no allocations allowed)
__device__ float g_xn [NTOK * DM];
__device__ float g_q  [NTOK * DM];
__device__ float g_k  [NTOK * DM];
__device__ float g_v  [NTOK * DM];
__device__ float g_att[NTOK * DM];
__device__ float g_x1 [NTOK * DM];
__device__ float g_xn2[NTOK * DM];
__device__ float g_ff [NTOK * DFF];

// ---------------------------------------------------------------------------
// LayerNorm (faithful: unbiased variance ddof=1, eps added to std, scalar affine)
// ---------------------------------------------------------------------------
__global__ __launch_bounds__(256)
void ln_kernel(const float* __restrict__ x, float* __restrict__ out,
               const float* __restrict__ ap, const float* __restrict__ bp)
{
    __shared__ float red[8];
    const int row = blockIdx.x;
    const int t   = threadIdx.x;
    const float* xr = x + (size_t)row * DM;

    float v[4];
    float s = 0.f;
#pragma unroll
    for (int e = 0; e < 4; e++) {
        v[e] = xr[t + e * 256];
        s += v[e];
    }
#pragma unroll
    for (int off = 16; off > 0; off >>= 1)
        s += __shfl_xor_sync(0xffffffffu, s, off);
    if ((t & 31) == 0) red[t >> 5] = s;
    __syncthreads();
    float tot = 0.f;
#pragma unroll
    for (int i = 0; i < 8; i++) tot += red[i];
    const float mean = tot * (1.0f / DM);

    float sq = 0.f;
#pragma unroll
    for (int e = 0; e < 4; e++) {
        float d = v[e] - mean;
        sq += d * d;
    }
#pragma unroll
    for (int off = 16; off > 0; off >>= 1)
        sq += __shfl_xor_sync(0xffffffffu, sq, off);
    __syncthreads();
    if ((t & 31) == 0) red[t >> 5] = sq;
    __syncthreads();
    float sqtot = 0.f;
#pragma unroll
    for (int i = 0; i < 8; i++) sqtot += red[i];

    const float var   = sqtot * (1.0f / (DM - 1));   // ddof=1
    const float denom = sqrtf(var) + 1e-5f;          // eps on std
    const float sc    = ap[0] / denom;
    const float beta  = bp[0];

    float* orow = out + (size_t)row * DM;
#pragma unroll
    for (int e = 0; e < 4; e++)
        orow[t + e * 256] = (v[e] - mean) * sc + beta;
}

// ---------------------------------------------------------------------------
// GEMM: C[M,N] = A[M,K] @ W[N,K]^T + bias[N] (+res[M,N]) (relu?)
// 128x128x16 tiles, 256 threads, 8x8 register blocking via FFMA2,
// double-buffered static smem (33.8 KB). A stored normal-transposed; broadcast
// pairs built in registers (pack_dup) to keep LDS traffic at 64 B/thread/kk.
// ---------------------------------------------------------------------------
#define BM 128
#define BN 128
#define BK 16
#define TSTR (BM + 4)         // 132 floats, rows 16B-aligned (528 B)

__device__ __forceinline__
void gemm_body(const float* __restrict__ A, const float* __restrict__ W,
               const float* __restrict__ bias, const float* __restrict__ res,
               float* __restrict__ C, int m0, int n0, int N, int K, int relu,
               float As[2][BK][TSTR], float Ws[2][BK][TSTR])
{
    const int t  = threadIdx.x;
    const int tx = t & 15;
    const int ty = t >> 4;

    u64 acc2[8][4];
#pragma unroll
    for (int i = 0; i < 8; i++)
#pragma unroll
        for (int j = 0; j < 4; j++) acc2[i][j] = 0ULL;

    const int lr = t >> 2;          // 0..63 row-in-group
    const int lc = (t & 3) << 2;    // 0,4,8,12 : k offset
    const int r0 = lr, r1 = lr + 64;

    const float* Ap0 = A + (size_t)(m0 + r0) * K + lc;
    const float* Ap1 = A + (size_t)(m0 + r1) * K + lc;
    const float* Wp0 = W + (size_t)(n0 + r0) * K + lc;
    const float* Wp1 = W + (size_t)(n0 + r1) * K + lc;

    // stage 0: load + store tile 0
    {
        float4 a0 = *(const float4*)Ap0;
        float4 a1 = *(const float4*)Ap1;
        float4 w0 = *(const float4*)Wp0;
        float4 w1 = *(const float4*)Wp1;
        As[0][lc + 0][r0] = a0.x; As[0][lc + 1][r0] = a0.y;
        As[0][lc + 2][r0] = a0.z; As[0][lc + 3][r0] = a0.w;
        As[0][lc + 0][r1] = a1.x; As[0][lc + 1][r1] = a1.y;
        As[0][lc + 2][r1] = a1.z; As[0][lc + 3][r1] = a1.w;
        Ws[0][lc + 0][r0] = w0.x; Ws[0][lc + 1][r0] = w0.y;
        Ws[0][lc + 2][r0] = w0.z; Ws[0][lc + 3][r0] = w0.w;
        Ws[0][lc + 0][r1] = w1.x; Ws[0][lc + 1][r1] = w1.y;
        Ws[0][lc + 2][r1] = w1.z; Ws[0][lc + 3][r1] = w1.w;
    }
    __syncthreads();

    int buf = 0;
    for (int k0 = 0; k0 < K; k0 += BK) {
        // prefetch next tile from gmem (registers)
        float4 pa0, pa1, pw0, pw1;
        const bool more = (k0 + BK < K);
        if (more) {
            pa0 = *(const float4*)(Ap0 + k0 + BK);
            pa1 = *(const float4*)(Ap1 + k0 + BK);
            pw0 = *(const float4*)(Wp0 + k0 + BK);
            pw1 = *(const float4*)(Wp1 + k0 + BK);
        }

        // compute current tile
#pragma unroll
        for (int kk = 0; kk < BK; kk++) {
            const float4* ap = (const float4*)&As[buf][kk][ty * 8];
            const ulonglong2* wp = (const ulonglong2*)&Ws[buf][kk][tx * 8];
            float4 a0 = ap[0], a1 = ap[1];
            ulonglong2 w01 = wp[0], w23 = wp[1];
            u64 ad[8] = {pack_dup(a0.x), pack_dup(a0.y), pack_dup(a0.z), pack_dup(a0.w),
                         pack_dup(a1.x), pack_dup(a1.y), pack_dup(a1.z), pack_dup(a1.w)};
            u64 wv[4] = {w01.x, w01.y, w23.x, w23.y};
#pragma unroll
            for (int i = 0; i < 8; i++)
#pragma unroll
                for (int j = 0; j < 4; j++)
                    acc2[i][j] = ffma2(ad[i], wv[j], acc2[i][j]);
        }

        // store next tile into the other stage, single barrier
        if (more) {
            const int nbuf = buf ^ 1;
            As[nbuf][lc + 0][r0] = pa0.x; As[nbuf][lc + 1][r0] = pa0.y;
            As[nbuf][lc + 2][r0] = pa0.z; As[nbuf][lc + 3][r0] = pa0.w;
            As[nbuf][lc + 0][r1] = pa1.x; As[nbuf][lc + 1][r1] = pa1.y;
            As[nbuf][lc + 2][r1] = pa1.z; As[nbuf][lc + 3][r1] = pa1.w;
            Ws[nbuf][lc + 0][r0] = pw0.x; Ws[nbuf][lc + 1][r0] = pw0.y;
            Ws[nbuf][lc + 2][r0] = pw0.z; Ws[nbuf][lc + 3][r0] = pw0.w;
            Ws[nbuf][lc + 0][r1] = pw1.x; Ws[nbuf][lc + 1][r1] = pw1.y;
            Ws[nbuf][lc + 2][r1] = pw1.z; Ws[nbuf][lc + 3][r1] = pw1.w;
            __syncthreads();
            buf = nbuf;
        }
    }

    // epilogue: unpack, bias (+res) (+relu), vector store
    const int nb = n0 + tx * 8;
    float4 b0 = *(const float4*)(bias + nb);
    float4 b1 = *(const float4*)(bias + nb + 4);
#pragma unroll
    for (int i = 0; i < 8; i++) {
        const int m = m0 + ty * 8 + i;
        float c[8];
        c[0] = lo2(acc2[i][0]) + b0.x; c[1] = hi2(acc2[i][0]) + b0.y;
        c[2] = lo2(acc2[i][1]) + b0.z; c[3] = hi2(acc2[i][1]) + b0.w;
        c[4] = lo2(acc2[i][2]) + b1.x; c[5] = hi2(acc2[i][2]) + b1.y;
        c[6] = lo2(acc2[i][3]) + b1.z; c[7] = hi2(acc2[i][3]) + b1.w;
        if (res) {
            const float4 q0 = *(const float4*)(res + (size_t)m * N + nb);
            const float4 q1 = *(const float4*)(res + (size_t)m * N + nb + 4);
            c[0] += q0.x; c[1] += q0.y; c[2] += q0.z; c[3] += q0.w;
            c[4] += q1.x; c[5] += q1.y; c[6] += q1.z; c[7] += q1.w;
        }
        if (relu) {
#pragma unroll
            for (int j = 0; j < 8; j++) c[j] = fmaxf(c[j], 0.f);
        }
        *(float4*)(C + (size_t)m * N + nb)     = make_float4(c[0], c[1], c[2], c[3]);
        *(float4*)(C + (size_t)m * N + nb + 4) = make_float4(c[4], c[5], c[6], c[7]);
    }
}

__global__ __launch_bounds__(256)
void gemm_kernel(const float* __restrict__ A, const float* __restrict__ W,
                 const float* __restrict__ bias, const float* __restrict__ res,
                 float* __restrict__ C, int M, int N, int K, int relu)
{
    __shared__ float As[2][BK][TSTR];
    __shared__ float Ws[2][BK][TSTR];
    gemm_body(A, W, bias, res, C,
              blockIdx.y * BM, blockIdx.x * BN, N, K, relu, As, Ws);
}

// fused QKV: blockIdx.x in [0,24): 8 N-tiles per matrix (N=1024 each)
__global__ __launch_bounds__(256)
void qkv_kernel(const float* __restrict__ A,
                const float* __restrict__ wq, const float* __restrict__ bq,
                const float* __restrict__ wk, const float* __restrict__ bk,
                const float* __restrict__ wv, const float* __restrict__ bv,
                float* __restrict__ q, float* __restrict__ k, float* __restrict__ v)
{
    __shared__ float As[2][BK][TSTR];
    __shared__ float Ws[2][BK][TSTR];

    const int mat = blockIdx.x >> 3;          // 0: q, 1: k, 2: v
    const int n0  = (blockIdx.x & 7) * BN;

    const float* W    = (mat == 0) ? wq : (mat == 1) ? wk : wv;
    const float* bias = (mat == 0) ? bq : (mat == 1) ? bk : bv;
    float*       C    = (mat == 0) ? q  : (mat == 1) ? k  : v;

    gemm_body(A, W, bias, nullptr, C,
              blockIdx.y * BM, n0, DM, DM, 0, As, Ws);
}

// ---------------------------------------------------------------------------
// Flash-style attention. grid = (S/64, H, B), 256 threads (16x16).
// 64 queries/block, 32 key tiles of 64, online softmax, FFMA2 mainloops.
// smem (~69.9 KB dynamic): Qs[d][i] Ks[d][j] Vs[j][d] Ps[j][i] all 64x68, Ms[64]
// ---------------------------------------------------------------------------
__global__ __launch_bounds__(256)
void attn_kernel(const float* __restrict__ q, const float* __restrict__ k,
                 const float* __restrict__ v, const int* __restrict__ mask,
                 float* __restrict__ out)
{
    extern __shared__ float sm[];
    float* Qs = sm;                 // [64][68] transposed (Qs[d*68+i])
    float* Ks = Qs + 64 * 68;       // [64][68] transposed (Ks[d*68+j])
    float* Vs = Ks + 64 * 68;       // [64][68] natural    (Vs[j*68+d])
    float* Ps = Vs + 64 * 68;       // [64][68] transposed (Ps[j*68+i])
    int*   Ms = (int*)(Ps + 64 * 68);

    const int b  = blockIdx.z;
    const int h  = blockIdx.y;
    const int qt = blockIdx.x;
    const int t  = threadIdx.x;
    const int tx = t & 15;
    const int ty = t >> 4;
    const float scale = 0.125f;     // 1/sqrt(64)

    const size_t base = (size_t)b * SEQ * DM + h * DK;

#pragma unroll
    for (int e = 0; e < 16; e++) {
        const int lin = e * 256 + t;
        const int i = lin >> 6, d = lin & 63;
        Qs[d * 68 + i] = q[base + (size_t)(qt * 64 + i) * DM + d];
    }

    float m_i[4], l_i[4];
    u64 o2[4][2];
#pragma unroll
    for (int a = 0; a < 4; a++) {
        m_i[a] = -INFINITY; l_i[a] = 0.f;
        o2[a][0] = 0ULL; o2[a][1] = 0ULL;
    }

    for (int kt = 0; kt < SEQ / 64; kt++) {
        __syncthreads();   // previous iter's Ps/Vs readers done
#pragma unroll
        for (int e = 0; e < 16; e++) {
            const int lin = e * 256 + t;
            const int j = lin >> 6, d = lin & 63;
            Ks[d * 68 + j] = k[base + (size_t)(kt * 64 + j) * DM + d];
            Vs[j * 68 + d] = v[base + (size_t)(kt * 64 + j) * DM + d];
        }
        if (t < 64) Ms[t] = mask[b * SEQ + kt * 64 + t];
        __syncthreads();

        // S = Q K^T : s2[a][c2], pairs along key dim
        u64 s2[4][2];
#pragma unroll
        for (int a = 0; a < 4; a++) { s2[a][0] = 0ULL; s2[a][1] = 0ULL; }
#pragma unroll
        for (int d = 0; d < 64; d++) {
            float4 qa = *(const float4*)&Qs[d * 68 + ty * 4];
            ulonglong2 kb = *(const ulonglong2*)&Ks[d * 68 + tx * 4];
            u64 q2[4] = {pack_dup(qa.x), pack_dup(qa.y), pack_dup(qa.z), pack_dup(qa.w)};
#pragma unroll
            for (int a = 0; a < 4; a++) {
                s2[a][0] = ffma2(q2[a], kb.x, s2[a][0]);
                s2[a][1] = ffma2(q2[a], kb.y, s2[a][1]);
            }
        }

        float s[4][4];
#pragma unroll
        for (int a = 0; a < 4; a++) {
            s[a][0] = lo2(s2[a][0]); s[a][1] = hi2(s2[a][0]);
            s[a][2] = lo2(s2[a][1]); s[a][3] = hi2(s2[a][1]);
#pragma unroll
            for (int c = 0; c < 4; c++) {
                float sv = s[a][c] * scale;
                if (Ms[tx * 4 + c] == 0) sv = -1e9f;
                s[a][c] = sv;
            }
        }

        // row max across 16 tx lanes
        float mt[4];
#pragma unroll
        for (int a = 0; a < 4; a++) {
            mt[a] = fmaxf(fmaxf(s[a][0], s[a][1]), fmaxf(s[a][2], s[a][3]));
#pragma unroll
            for (int off = 1; off <= 8; off <<= 1)
                mt[a] = fmaxf(mt[a], __shfl_xor_sync(0xffffffffu, mt[a], off));
        }

#pragma unroll
        for (int a = 0; a < 4; a++) {
            const float mnew = fmaxf(m_i[a], mt[a]);
            float ps = 0.f;
#pragma unroll
            for (int c = 0; c < 4; c++) {
                const float p = __expf(s[a][c] - mnew);
                s[a][c] = p;
                ps += p;
            }
#pragma unroll
            for (int off = 1; off <= 8; off <<= 1)
                ps += __shfl_xor_sync(0xffffffffu, ps, off);
            const float f = __expf(m_i[a] - mnew);
            l_i[a] = l_i[a] * f + ps;
            m_i[a] = mnew;
            const u64 f2 = pack_dup(f);
            o2[a][0] = fmul2(o2[a][0], f2);
            o2[a][1] = fmul2(o2[a][1], f2);
        }

        // stage P transposed
#pragma unroll
        for (int a = 0; a < 4; a++)
#pragma unroll
            for (int c = 0; c < 4; c++)
                Ps[(tx * 4 + c) * 68 + ty * 4 + a] = s[a][c];
        __syncthreads();

        // O += P V : pairs along head dim
#pragma unroll
        for (int j = 0; j < 64; j++) {
            float4 pa = *(const float4*)&Ps[j * 68 + ty * 4];
            ulonglong2 vb = *(const ulonglong2*)&Vs[j * 68 + tx * 4];
            u64 p2[4] = {pack_dup(pa.x), pack_dup(pa.y), pack_dup(pa.z), pack_dup(pa.w)};
#pragma unroll
            for (int a = 0; a < 4; a++) {
                o2[a][0] = ffma2(p2[a], vb.x, o2[a][0]);
                o2[a][1] = ffma2(p2[a], vb.y, o2[a][1]);
            }
        }
    }

#pragma unroll
    for (int a = 0; a < 4; a++) {
        const float inv = 1.0f / l_i[a];
        const int qrow = qt * 64 + ty * 4 + a;
        float* op = out + ((size_t)b * SEQ + qrow) * DM + h * DK + tx * 4;
        op[0] = lo2(o2[a][0]) * inv;
        op[1] = hi2(o2[a][0]) * inv;
        op[2] = lo2(o2[a][1]) * inv;
        op[3] = hi2(o2[a][1]) * inv;
    }
}

// ---------------------------------------------------------------------------
// launcher
// ---------------------------------------------------------------------------
extern "C" void kernel_launch(void* const* d_in, const int* in_sizes, int n_in,
                              void* d_out, int out_size)
{
    (void)in_sizes; (void)n_in; (void)out_size;

    const float* x    = (const float*)d_in[0];
    const int*   mask = (const int*)  d_in[1];
    const float* wq   = (const float*)d_in[2];
    const float* bq   = (const float*)d_in[3];
    const float* wk   = (const float*)d_in[4];
    const float* bk   = (const float*)d_in[5];
    const float* wv   = (const float*)d_in[6];
    const float* bv   = (const float*)d_in[7];
    const float* wo   = (const float*)d_in[8];
    const float* bo   = (const float*)d_in[9];
    const float* w1   = (const float*)d_in[10];
    const float* b1   = (const float*)d_in[11];
    const float* w2   = (const float*)d_in[12];
    const float* b2   = (const float*)d_in[13];
    const float* a1   = (const float*)d_in[14];
    const float* n1   = (const float*)d_in[15];
    const float* a2   = (const float*)d_in[16];
    const float* n2   = (const float*)d_in[17];
    float* out = (float*)d_out;

    float *xn, *q, *k, *v, *att, *x1, *xn2, *ff;
    cudaGetSymbolAddress((void**)&xn,  g_xn);
    cudaGetSymbolAddress((void**)&q,   g_q);
    cudaGetSymbolAddress((void**)&k,   g_k);
    cudaGetSymbolAddress((void**)&v,   g_v);
    cudaGetSymbolAddress((void**)&att, g_att);
    cudaGetSymbolAddress((void**)&x1,  g_x1);
    cudaGetSymbolAddress((void**)&xn2, g_xn2);
    cudaGetSymbolAddress((void**)&ff,  g_ff);

    const int attn_smem = (4 * 64 * 68) * 4 + 64 * 4;   // ~69.9 KB
    cudaFuncSetAttribute((const void*)attn_kernel,
                         cudaFuncAttributeMaxDynamicSharedMemorySize, attn_smem);

    // LN1
    ln_kernel<<<NTOK, 256>>>(x, xn, a1, n1);

    // fused Q,K,V projections
    {
        dim3 g(24, NTOK / BM);
        qkv_kernel<<<g, 256>>>(xn, wq, bq, wk, bk, wv, bv, q, k, v);
    }

    // attention
    {
        dim3 g(SEQ / 64, NH, 2);
        attn_kernel<<<g, 256, attn_smem>>>(q, k, v, mask, att);
    }

    // O projection + residual
    {
        dim3 g(DM / BN, NTOK / BM);
        gemm_kernel<<<g, 256>>>(att, wo, bo, x, x1, NTOK, DM, DM, 0);
    }

    // LN2
    ln_kernel<<<NTOK, 256>>>(x1, xn2, a2, n2);

    // FFN
    {
        dim3 g1(DFF / BN, NTOK / BM);
        gemm_kernel<<<g1, 256>>>(xn2, w1, b1, nullptr, ff, NTOK, DFF, DM, 1);
        dim3 g2(DM / BN, NTOK / BM);
        gemm_kernel<<<g2, 256>>>(ff, w2, b2, x1, out, NTOK, DM, DFF, 0);
    }
}